// round 11
// baseline (speedup 1.0000x reference)
#include <cuda_runtime.h>
#include <cuda_fp16.h>
#include <cstdint>

// Problem sizes
static constexpr int NTOK = 8192;
static constexpr int DM   = 1024;
static constexpr int NEXP = 8;
static constexpr int RLO  = 16;
static constexpr int KC   = 1152;   // 1024 + 128 lora-combine columns

// Scratch (device globals; no runtime allocation allowed)
__device__ __half g_xh[(long)NTOK * KC];       // [ x | c ]        (rows: token)
__device__ __half g_wh[(long)DM * KC];         // [ W_base | B^T ] (rows: out dim)
__device__ __half g_ah[128L * DM];             // ah[j][k] = A[e][k][r], j=e*16+r
__device__ float  g_hall[2L * NTOK * 128];     // split-K partial h (2 halves)

// ---------------------------------------------------------------------------
// Helpers
// ---------------------------------------------------------------------------
static __device__ __forceinline__ uint32_t smem_u32(const void* p) {
    uint32_t a;
    asm("{ .reg .u64 t; cvta.to.shared.u64 t, %1; cvt.u32.u64 %0, t; }" : "=r"(a) : "l"(p));
    return a;
}

#define CP_ASYNC16(saddr, gptr) \
    asm volatile("cp.async.cg.shared.global [%0], [%1], 16;" :: "r"(saddr), "l"(gptr))
#define CP_COMMIT() asm volatile("cp.async.commit_group;" ::: "memory")
#define CP_WAIT1()  asm volatile("cp.async.wait_group 1;" ::: "memory")

// m16n8k16 fp16 MMA, fp32 accumulate
#define MMA_F16(d, a, b) \
    asm volatile("mma.sync.aligned.m16n8k16.row.col.f32.f16.f16.f32 " \
        "{%0,%1,%2,%3}, {%4,%5,%6,%7}, {%8,%9}, {%0,%1,%2,%3};" \
        : "+f"((d)[0]), "+f"((d)[1]), "+f"((d)[2]), "+f"((d)[3]) \
        : "r"((a)[0]), "r"((a)[1]), "r"((a)[2]), "r"((a)[3]), \
          "r"((b)[0]), "r"((b)[1]))

#define LDMX4(r0, r1, r2, r3, addr) \
    asm volatile("ldmatrix.sync.aligned.m8n8.x4.shared.b16 {%0,%1,%2,%3}, [%4];" \
        : "=r"(r0), "=r"(r1), "=r"(r2), "=r"(r3) : "r"(addr))

// ---------------------------------------------------------------------------
// Fused prep kernel (single launch). x/W segments: 4 float4 per thread
// (coalesced per round, MLP=4). Layout: [x16][W16][B][A]
// ---------------------------------------------------------------------------
static constexpr long NX16 = (long)NTOK * DM / 16;  // 524288 threads
static constexpr long NW16 = (long)DM * DM / 16;    // 65536 threads
static constexpr long NB   = 128L * DM;             // 131072
static constexpr long NA   = 128L * DM;             // 131072
static constexpr long NPREP = NX16 + NW16 + NB + NA;

__global__ void prep_all_kernel(const float* __restrict__ x,
                                const float* __restrict__ Wb,
                                const float* __restrict__ B,
                                const float* __restrict__ A) {
    long i = (long)blockIdx.x * blockDim.x + threadIdx.x;
    if (i < NX16) {
        long base4 = (i >> 8) * 1024 + (i & 255);
#pragma unroll
        for (int q = 0; q < 4; q++) {
            long i4 = base4 + q * 256;
            long n = i4 >> 8, d = (i4 & 255) * 4;
            float4 v = *(const float4*)(x + i4 * 4);
            __half2* dst = (__half2*)(g_xh + n * KC + d);
            dst[0] = __floats2half2_rn(v.x, v.y);
            dst[1] = __floats2half2_rn(v.z, v.w);
        }
        return;
    }
    i -= NX16;
    if (i < NW16) {
        long base4 = (i >> 8) * 1024 + (i & 255);
#pragma unroll
        for (int q = 0; q < 4; q++) {
            long i4 = base4 + q * 256;
            long n = i4 >> 8, k = (i4 & 255) * 4;
            float4 v = *(const float4*)(Wb + i4 * 4);
            __half2* dst = (__half2*)(g_wh + n * KC + k);
            dst[0] = __floats2half2_rn(v.x, v.y);
            dst[1] = __floats2half2_rn(v.z, v.w);
        }
        return;
    }
    i -= NW16;
    if (i < NB) {   // B[e][r][d] -> g_wh[d][1024 + j], j = e*16+r = i>>10
        int j = (int)(i >> 10), d = (int)(i & 1023);
        g_wh[(long)d * KC + 1024 + j] = __float2half_rn(B[i]);
        return;
    }
    i -= NB;
    if (i < NA) {   // A[e][d][r] -> g_ah[j][k] = A[e][k][r]
        int j = (int)(i >> 10), k = (int)(i & 1023);
        int e = j >> 4, r = j & 15;
        g_ah[(long)j * DM + k] = __float2half_rn(A[((long)e * DM + k) * RLO + r]);
    }
}

// ---------------------------------------------------------------------------
// Gating + lora-combine assembly (fp32 math, one warp per token).
// Reads fp32 x/Wg for exact top-k; h = sum of split-K halves of g_hall.
// ---------------------------------------------------------------------------
__global__ void __launch_bounds__(256) gate_c_kernel(const float* __restrict__ x,
                                                     const float* __restrict__ Wg) {
    int warp = (blockIdx.x * blockDim.x + threadIdx.x) >> 5;
    int lane = threadIdx.x & 31;
    if (warp >= NTOK) return;
    const float* xr = x + (long)warp * DM;

    float acc[NEXP];
#pragma unroll
    for (int e = 0; e < NEXP; e++) acc[e] = 0.f;
    for (int d = lane; d < DM; d += 32) {
        float xv = xr[d];
#pragma unroll
        for (int e = 0; e < NEXP; e++) acc[e] = fmaf(xv, Wg[e * DM + d], acc[e]);
    }
#pragma unroll
    for (int e = 0; e < NEXP; e++)
#pragma unroll
        for (int s = 16; s > 0; s >>= 1) acc[e] += __shfl_xor_sync(0xFFFFFFFFu, acc[e], s);

    float v0 = -1e30f; int e0 = 0;
#pragma unroll
    for (int e = 0; e < NEXP; e++) if (acc[e] > v0) { v0 = acc[e]; e0 = e; }
    float v1 = -1e30f; int e1 = 0;
#pragma unroll
    for (int e = 0; e < NEXP; e++) if (e != e0 && acc[e] > v1) { v1 = acc[e]; e1 = e; }
    float b  = expf(v1 - v0);
    float w0 = 1.f / (1.f + b);
    float w1 = b * w0;

    __half* cp = g_xh + (long)warp * KC + 1024;
    for (int i = lane; i < 128; i += 32) cp[i] = __float2half_rn(0.f);
    __syncwarp();
    {
        int j = lane >> 4;
        int r = lane & 15;
        int e = j ? e1 : e0;
        float w = j ? w1 : w0;
        long off = (long)warp * 128 + e * RLO + r;
        float h = g_hall[off] + g_hall[(long)NTOK * 128 + off];
        cp[e * RLO + r] = __float2half_rn(w * h);
    }
}

// ---------------------------------------------------------------------------
// FP16 GEMM: C[m0+BM, n0+BN] = A[m,kslice] * B[n,kslice]^T (+bias), fp32 acc.
// BM = WM*MI*16, BN = WN*NJ*8. 8 warps (WM x WN), warp tile (MI*16)x(NJ*8).
// 2-stage cp.async, ldmatrix fragments. OCC = CTAs/SM. blockIdx.z = K-split
// index (kslice = [z*ktiles*64, ...)); C shifted by z*csplit.
// ---------------------------------------------------------------------------
static constexpr int LDH = 72;                          // row pad: 64+8 halves
static constexpr int NSTAGE = 2;

template <int WM, int WN, int MI, int NJ, int BIAS, int OCC>
__global__ void __launch_bounds__(256, OCC)
gemm_f16(const __half* __restrict__ A, long lda,
         const __half* __restrict__ Bm, long ldb,
         float* __restrict__ C, long ldc,
         const float* __restrict__ bias, int ktiles, long csplit) {
    constexpr int BM = WM * MI * 16;
    constexpr int BN = WN * NJ * 8;
    constexpr int STAGE_BYTES = (BM + BN) * LDH * 2;

    extern __shared__ __align__(16) __half smem[];

    const int tid  = threadIdx.x;
    const int wid  = tid >> 5;
    const int lane = tid & 31;
    const int wm   = wid / WN;
    const int wn   = wid % WN;
    const int g    = lane >> 2;
    const int t4   = lane & 3;
    const int m0   = blockIdx.x * BM;
    const int n0   = blockIdx.y * BN;
    const int kbase = blockIdx.z * ktiles;

    const uint32_t sbase = smem_u32(smem);
    const __half* Ab = A + (long)m0 * lda;
    const __half* Bb = Bm + (long)n0 * ldb;
    C += (long)blockIdx.z * csplit;

    auto load_stage = [&](int kt, int stg) {
        const uint32_t sa = sbase + (uint32_t)stg * STAGE_BYTES;
        const uint32_t sb = sa + BM * LDH * 2;
        const __half* Asrc = Ab + (long)(kbase + kt) * 64;
        const __half* Bsrc = Bb + (long)(kbase + kt) * 64;
#pragma unroll
        for (int c = 0; c < BM * 8 / 256; c++) {
            int idx = c * 256 + tid;
            int row = idx >> 3, q = idx & 7;
            CP_ASYNC16(sa + (uint32_t)(row * LDH + q * 8) * 2,
                       Asrc + (long)row * lda + q * 8);
        }
#pragma unroll
        for (int c = 0; c < BN * 8 / 256; c++) {
            int idx = c * 256 + tid;
            int row = idx >> 3, q = idx & 7;
            CP_ASYNC16(sb + (uint32_t)(row * LDH + q * 8) * 2,
                       Bsrc + (long)row * ldb + q * 8);
        }
        CP_COMMIT();
    };

    const int lrow = lane & 15;
    const int lcol = (lane >> 4) * 8;
    const uint32_t aoffh = (uint32_t)((wm * (MI * 16) + lrow) * LDH + lcol);
    const uint32_t boffh = (uint32_t)(BM * LDH + (wn * (NJ * 8) + lrow) * LDH + lcol);

    float acc[MI][NJ][4];
#pragma unroll
    for (int i = 0; i < MI; i++)
#pragma unroll
        for (int j = 0; j < NJ; j++)
#pragma unroll
            for (int r = 0; r < 4; r++) acc[i][j][r] = 0.f;

    load_stage(0, 0);

    for (int kt = 0; kt < ktiles; kt++) {
        if (kt + 1 < ktiles) load_stage(kt + 1, (kt + 1) & 1);
        else CP_COMMIT();
        CP_WAIT1();
        __syncthreads();

        const uint32_t sa = sbase + (uint32_t)(kt & 1) * STAGE_BYTES;
#pragma unroll
        for (int ks = 0; ks < 4; ks++) {
            const uint32_t ksh = (uint32_t)(ks * 16) * 2;
            uint32_t a[MI][4];
#pragma unroll
            for (int i = 0; i < MI; i++)
                LDMX4(a[i][0], a[i][1], a[i][2], a[i][3],
                      sa + (aoffh + (uint32_t)(i * 16) * LDH) * 2 + ksh);
            uint32_t b[NJ][2];
#pragma unroll
            for (int jp = 0; jp < NJ / 2; jp++)
                LDMX4(b[jp * 2][0], b[jp * 2 + 1][0], b[jp * 2][1], b[jp * 2 + 1][1],
                      sa + (boffh + (uint32_t)(jp * 16) * LDH) * 2 + ksh);
#pragma unroll
            for (int i = 0; i < MI; i++)
#pragma unroll
                for (int j = 0; j < NJ; j++)
                    MMA_F16(acc[i][j], a[i], b[j]);
        }
        __syncthreads();
    }

    // Epilogue
#pragma unroll
    for (int i = 0; i < MI; i++) {
        int row0 = m0 + wm * (MI * 16) + i * 16 + g;
#pragma unroll
        for (int j = 0; j < NJ; j++) {
            int col = n0 + wn * (NJ * 8) + j * 8 + 2 * t4;
            float bx = 0.f, by = 0.f;
            if (BIAS) { bx = bias[col]; by = bias[col + 1]; }
            float2 v0 = { acc[i][j][0] + bx, acc[i][j][1] + by };
            float2 v1 = { acc[i][j][2] + bx, acc[i][j][3] + by };
            *(float2*)(C + (long)row0 * ldc + col)       = v0;
            *(float2*)(C + (long)(row0 + 8) * ldc + col) = v1;
        }
    }
}

// GEMM<0>: BM=64, BN=128 (WM=2, WN=4, MI=2, NJ=4), OCC=3, split-K x2
// GEMM<1>: BM=128, BN=64 (WM=4, WN=2, MI=2, NJ=4), OCC=4 (proven 70.8us)
static constexpr int SMEM_B0 = NSTAGE * (64 + 128) * LDH * 2;  // 55296
static constexpr int SMEM_B1 = NSTAGE * (128 + 64) * LDH * 2;  // 55296

// ---------------------------------------------------------------------------
// Launch
// ---------------------------------------------------------------------------
extern "C" void kernel_launch(void* const* d_in, const int* in_sizes, int n_in,
                              void* d_out, int out_size) {
    const float* x    = (const float*)d_in[0];
    const float* Wg   = (const float*)d_in[1];
    const float* A    = (const float*)d_in[2];
    const float* B    = (const float*)d_in[3];
    const float* Wb   = (const float*)d_in[4];
    const float* bias = (const float*)d_in[5];
    float* out = (float*)d_out;

    static bool attr_done = false;
    if (!attr_done) {
        cudaFuncSetAttribute((const void*)gemm_f16<2, 4, 2, 4, 0, 3>,
                             cudaFuncAttributeMaxDynamicSharedMemorySize, SMEM_B0);
        cudaFuncSetAttribute((const void*)gemm_f16<4, 2, 2, 4, 1, 4>,
                             cudaFuncAttributeMaxDynamicSharedMemorySize, SMEM_B1);
        attr_done = true;
    }

    __half *xh, *wh, *ah;
    float* hall;
    cudaGetSymbolAddress((void**)&xh, g_xh);
    cudaGetSymbolAddress((void**)&wh, g_wh);
    cudaGetSymbolAddress((void**)&ah, g_ah);
    cudaGetSymbolAddress((void**)&hall, g_hall);

    // 1) fp16 operand staging (single launch, MLP-4 vectorized x/W)
    prep_all_kernel<<<(int)((NPREP + 255) / 256), 256>>>(x, Wb, B, A);

    // 2) h = x @ A for all experts, split-K x2 (256 CTAs, K=512 each)
    gemm_f16<2, 4, 2, 4, 0, 3><<<dim3(NTOK / 64, 1, 2), 256, SMEM_B0>>>(
        xh, KC, ah, DM, hall, 128, nullptr, (DM / 64) / 2, (long)NTOK * 128);

    // 3) gating + combine coefficients into g_xh tail columns (chip-wide)
    gate_c_kernel<<<(NTOK * 32) / 256, 256>>>(x, Wg);

    // 4) fused output GEMM: out = [x|c] @ [W|Bt]^T + bias  (8192 x 1024 x 1152)
    gemm_f16<4, 2, 2, 4, 1, 4><<<dim3(NTOK / 128, DM / 64, 1), 256, SMEM_B1>>>(
        xh, KC, wh, KC, out, DM, bias, KC / 64, 0);
}

// round 12
// speedup vs baseline: 1.0357x; 1.0357x over previous
#include <cuda_runtime.h>
#include <cuda_fp16.h>
#include <cstdint>

// Problem sizes
static constexpr int NTOK = 8192;
static constexpr int DM   = 1024;
static constexpr int NEXP = 8;
static constexpr int RLO  = 16;
static constexpr int KC   = 1152;   // 1024 + 128 lora-combine columns

// Scratch (device globals; no runtime allocation allowed)
__device__ __half g_xh[(long)NTOK * KC];    // [ x | c ]        (rows: token)
__device__ __half g_wh[(long)DM * KC];      // [ W_base | B^T ] (rows: out dim)
__device__ __half g_ah[128L * DM];          // ah[j][k] = A[e][k][r], j=e*16+r
__device__ float4 g_gate[NTOK];             // {w0, w1, bits(e0), bits(e1)}

// ---------------------------------------------------------------------------
// Helpers
// ---------------------------------------------------------------------------
static __device__ __forceinline__ uint32_t smem_u32(const void* p) {
    uint32_t a;
    asm("{ .reg .u64 t; cvta.to.shared.u64 t, %1; cvt.u32.u64 %0, t; }" : "=r"(a) : "l"(p));
    return a;
}

#define CP_ASYNC16(saddr, gptr) \
    asm volatile("cp.async.cg.shared.global [%0], [%1], 16;" :: "r"(saddr), "l"(gptr))
#define CP_COMMIT() asm volatile("cp.async.commit_group;" ::: "memory")
#define CP_WAIT1()  asm volatile("cp.async.wait_group 1;" ::: "memory")

// m16n8k16 fp16 MMA, fp32 accumulate
#define MMA_F16(d, a, b) \
    asm volatile("mma.sync.aligned.m16n8k16.row.col.f32.f16.f16.f32 " \
        "{%0,%1,%2,%3}, {%4,%5,%6,%7}, {%8,%9}, {%0,%1,%2,%3};" \
        : "+f"((d)[0]), "+f"((d)[1]), "+f"((d)[2]), "+f"((d)[3]) \
        : "r"((a)[0]), "r"((a)[1]), "r"((a)[2]), "r"((a)[3]), \
          "r"((b)[0]), "r"((b)[1]))

#define LDMX4(r0, r1, r2, r3, addr) \
    asm volatile("ldmatrix.sync.aligned.m8n8.x4.shared.b16 {%0,%1,%2,%3}, [%4];" \
        : "=r"(r0), "=r"(r1), "=r"(r2), "=r"(r3) : "r"(addr))

// ---------------------------------------------------------------------------
// Fused prep + gate-logit kernel (single launch).
// Segments (all boundaries 256-thread-block aligned):
//   [x MLP4: 524288][W MLP4: 65536][B: 131072][A: 131072][logits: 262144]
// ---------------------------------------------------------------------------
static constexpr long NX16 = (long)NTOK * DM / 16;  // 524288
static constexpr long NW16 = (long)DM * DM / 16;    // 65536
static constexpr long NB   = 128L * DM;             // 131072
static constexpr long NA   = 128L * DM;             // 131072
static constexpr long NL   = (long)NTOK * 32;       // 262144 (warp per token)
static constexpr long NPREP = NX16 + NW16 + NB + NA + NL;

__global__ void prep_logit_kernel(const float* __restrict__ x,
                                  const float* __restrict__ Wb,
                                  const float* __restrict__ B,
                                  const float* __restrict__ A,
                                  const float* __restrict__ Wg) {
    long i = (long)blockIdx.x * blockDim.x + threadIdx.x;
    if (i < NX16) {
        long base4 = (i >> 8) * 1024 + (i & 255);
#pragma unroll
        for (int q = 0; q < 4; q++) {
            long i4 = base4 + q * 256;
            long n = i4 >> 8, d = (i4 & 255) * 4;
            float4 v = *(const float4*)(x + i4 * 4);
            __half2* dst = (__half2*)(g_xh + n * KC + d);
            dst[0] = __floats2half2_rn(v.x, v.y);
            dst[1] = __floats2half2_rn(v.z, v.w);
        }
        return;
    }
    i -= NX16;
    if (i < NW16) {
        long base4 = (i >> 8) * 1024 + (i & 255);
#pragma unroll
        for (int q = 0; q < 4; q++) {
            long i4 = base4 + q * 256;
            long n = i4 >> 8, k = (i4 & 255) * 4;
            float4 v = *(const float4*)(Wb + i4 * 4);
            __half2* dst = (__half2*)(g_wh + n * KC + k);
            dst[0] = __floats2half2_rn(v.x, v.y);
            dst[1] = __floats2half2_rn(v.z, v.w);
        }
        return;
    }
    i -= NW16;
    if (i < NB) {   // B[e][r][d] -> g_wh[d][1024 + j], j = e*16+r = i>>10
        int j = (int)(i >> 10), d = (int)(i & 1023);
        g_wh[(long)d * KC + 1024 + j] = __float2half_rn(B[i]);
        return;
    }
    i -= NB;
    if (i < NA) {   // A[e][d][r] -> g_ah[j][k] = A[e][k][r]
        int j = (int)(i >> 10), k = (int)(i & 1023);
        int e = j >> 4, r = j & 15;
        g_ah[(long)j * DM + k] = __float2half_rn(A[((long)e * DM + k) * RLO + r]);
        return;
    }
    i -= NA;
    if (i < NL) {   // fp32 gate logits + top-2 softmax -> g_gate record
        int warp = (int)(i >> 5);
        int lane = threadIdx.x & 31;            // boundary is 32-aligned
        const float* xr = x + (long)warp * DM;

        float acc[NEXP];
#pragma unroll
        for (int e = 0; e < NEXP; e++) acc[e] = 0.f;
        for (int d = lane; d < DM; d += 32) {
            float xv = xr[d];
#pragma unroll
            for (int e = 0; e < NEXP; e++) acc[e] = fmaf(xv, Wg[e * DM + d], acc[e]);
        }
#pragma unroll
        for (int e = 0; e < NEXP; e++)
#pragma unroll
            for (int s = 16; s > 0; s >>= 1)
                acc[e] += __shfl_xor_sync(0xFFFFFFFFu, acc[e], s);

        float v0 = -1e30f; int e0 = 0;
#pragma unroll
        for (int e = 0; e < NEXP; e++) if (acc[e] > v0) { v0 = acc[e]; e0 = e; }
        float v1 = -1e30f; int e1 = 0;
#pragma unroll
        for (int e = 0; e < NEXP; e++) if (e != e0 && acc[e] > v1) { v1 = acc[e]; e1 = e; }
        float b  = expf(v1 - v0);
        float w0 = 1.f / (1.f + b);
        float w1 = b * w0;
        if (lane == 0)
            g_gate[warp] = make_float4(w0, w1, __int_as_float(e0), __int_as_float(e1));
    }
}

static constexpr int LDH = 72;                          // row pad: 64+8 halves
static constexpr int NSTAGE = 2;

// ---------------------------------------------------------------------------
// GEMM0 + gate epilogue: h[64x128] = x @ A^T (fp16 MMA, fp32 accum); epilogue
// scales h by precomputed gate weights and writes fp16 c into g_xh tail.
// BM=64, BN=128, 8 warps (2 x 4), warp tile 32x32, 2-stage, OCC=3.
// ---------------------------------------------------------------------------
__global__ void __launch_bounds__(256, 3)
gemm0_gate(const __half* __restrict__ Am, const __half* __restrict__ Bm) {
    constexpr int BM = 64, BN = 128, MI = 2, NJ = 4;
    constexpr int KT = DM / 64;                         // 16
    constexpr int STAGE_BYTES = (BM + BN) * LDH * 2;    // 27648

    extern __shared__ __align__(16) __half smem[];

    const int tid  = threadIdx.x;
    const int wid  = tid >> 5;
    const int lane = tid & 31;
    const int wm   = wid >> 2;        // 0..1
    const int wn   = wid & 3;         // 0..3
    const int g    = lane >> 2;
    const int t4   = lane & 3;
    const int m0   = blockIdx.x * BM;

    const uint32_t sbase = smem_u32(smem);
    const __half* Ab = Am + (long)m0 * KC;

    auto load_stage = [&](int kt, int stg) {
        const uint32_t sa = sbase + (uint32_t)stg * STAGE_BYTES;
        const uint32_t sb = sa + BM * LDH * 2;
        const __half* Asrc = Ab + (long)kt * 64;
        const __half* Bsrc = Bm + (long)kt * 64;
#pragma unroll
        for (int c = 0; c < BM * 8 / 256; c++) {        // 2
            int idx = c * 256 + tid;
            int row = idx >> 3, q = idx & 7;
            CP_ASYNC16(sa + (uint32_t)(row * LDH + q * 8) * 2,
                       Asrc + (long)row * KC + q * 8);
        }
#pragma unroll
        for (int c = 0; c < BN * 8 / 256; c++) {        // 4
            int idx = c * 256 + tid;
            int row = idx >> 3, q = idx & 7;
            CP_ASYNC16(sb + (uint32_t)(row * LDH + q * 8) * 2,
                       Bsrc + (long)row * DM + q * 8);
        }
        CP_COMMIT();
    };

    const int lrow = lane & 15;
    const int lcol = (lane >> 4) * 8;
    const uint32_t aoffh = (uint32_t)((wm * 32 + lrow) * LDH + lcol);
    const uint32_t boffh = (uint32_t)(BM * LDH + (wn * 32 + lrow) * LDH + lcol);

    float acc[MI][NJ][4];
#pragma unroll
    for (int i = 0; i < MI; i++)
#pragma unroll
        for (int j = 0; j < NJ; j++)
#pragma unroll
            for (int r = 0; r < 4; r++) acc[i][j][r] = 0.f;

    load_stage(0, 0);

    for (int kt = 0; kt < KT; kt++) {
        if (kt + 1 < KT) load_stage(kt + 1, (kt + 1) & 1);
        else CP_COMMIT();
        CP_WAIT1();
        __syncthreads();

        const uint32_t sa = sbase + (uint32_t)(kt & 1) * STAGE_BYTES;
#pragma unroll
        for (int ks = 0; ks < 4; ks++) {
            const uint32_t ksh = (uint32_t)(ks * 16) * 2;
            uint32_t a[MI][4];
#pragma unroll
            for (int i = 0; i < MI; i++)
                LDMX4(a[i][0], a[i][1], a[i][2], a[i][3],
                      sa + (aoffh + (uint32_t)(i * 16) * LDH) * 2 + ksh);
            uint32_t b[NJ][2];
#pragma unroll
            for (int jp = 0; jp < NJ / 2; jp++)
                LDMX4(b[jp * 2][0], b[jp * 2 + 1][0], b[jp * 2][1], b[jp * 2 + 1][1],
                      sa + (boffh + (uint32_t)(jp * 16) * LDH) * 2 + ksh);
#pragma unroll
            for (int i = 0; i < MI; i++)
#pragma unroll
                for (int j = 0; j < NJ; j++)
                    MMA_F16(acc[i][j], a[i], b[j]);
        }
        __syncthreads();
    }

    // Gate epilogue: c[token][col] = w(token, col>>4) * h ; write fp16 pairs.
#pragma unroll
    for (int i = 0; i < MI; i++) {
        int t0 = m0 + wm * 32 + i * 16 + g;
        int t1 = t0 + 8;
        float4 r0 = g_gate[t0];
        float4 r1 = g_gate[t1];
        int e0a = __float_as_int(r0.z), e1a = __float_as_int(r0.w);
        int e0b = __float_as_int(r1.z), e1b = __float_as_int(r1.w);
#pragma unroll
        for (int j = 0; j < NJ; j++) {
            int col = wn * 32 + j * 8 + 2 * t4;
            int e = col >> 4;                  // col, col+1 share the expert
            float wa = (e == e0a) ? r0.x : ((e == e1a) ? r0.y : 0.f);
            float wb = (e == e0b) ? r1.x : ((e == e1b) ? r1.y : 0.f);
            *(__half2*)(g_xh + (long)t0 * KC + 1024 + col) =
                __floats2half2_rn(wa * acc[i][j][0], wa * acc[i][j][1]);
            *(__half2*)(g_xh + (long)t1 * KC + 1024 + col) =
                __floats2half2_rn(wb * acc[i][j][2], wb * acc[i][j][3]);
        }
    }
}

// ---------------------------------------------------------------------------
// Output GEMM (round-10 proven, 70.8us): C = [x|c] @ [W|Bt]^T + bias.
// BM=128, BN=64, 8 warps (4 x 2), warp tile 32x32, 2-stage, OCC=4.
// ---------------------------------------------------------------------------
__global__ void __launch_bounds__(256, 4)
gemm1(const __half* __restrict__ A, const __half* __restrict__ Bm,
      float* __restrict__ C, const float* __restrict__ bias) {
    constexpr int BM = 128, BN = 64, MI = 2, NJ = 4;
    constexpr int KT = KC / 64;                         // 18
    constexpr int STAGE_BYTES = (BM + BN) * LDH * 2;    // 27648

    extern __shared__ __align__(16) __half smem[];

    const int tid  = threadIdx.x;
    const int wid  = tid >> 5;
    const int lane = tid & 31;
    const int wm   = wid >> 1;        // 0..3
    const int wn   = wid & 1;         // 0..1
    const int g    = lane >> 2;
    const int t4   = lane & 3;
    const int m0   = blockIdx.x * BM;
    const int n0   = blockIdx.y * BN;

    const uint32_t sbase = smem_u32(smem);
    const __half* Ab = A + (long)m0 * KC;
    const __half* Bb = Bm + (long)n0 * KC;

    auto load_stage = [&](int kt, int stg) {
        const uint32_t sa = sbase + (uint32_t)stg * STAGE_BYTES;
        const uint32_t sb = sa + BM * LDH * 2;
        const __half* Asrc = Ab + (long)kt * 64;
        const __half* Bsrc = Bb + (long)kt * 64;
#pragma unroll
        for (int c = 0; c < BM * 8 / 256; c++) {
            int idx = c * 256 + tid;
            int row = idx >> 3, q = idx & 7;
            CP_ASYNC16(sa + (uint32_t)(row * LDH + q * 8) * 2,
                       Asrc + (long)row * KC + q * 8);
        }
#pragma unroll
        for (int c = 0; c < BN * 8 / 256; c++) {
            int idx = c * 256 + tid;
            int row = idx >> 3, q = idx & 7;
            CP_ASYNC16(sb + (uint32_t)(row * LDH + q * 8) * 2,
                       Bsrc + (long)row * KC + q * 8);
        }
        CP_COMMIT();
    };

    const int lrow = lane & 15;
    const int lcol = (lane >> 4) * 8;
    const uint32_t aoffh = (uint32_t)((wm * 32 + lrow) * LDH + lcol);
    const uint32_t boffh = (uint32_t)(BM * LDH + (wn * 32 + lrow) * LDH + lcol);

    float acc[MI][NJ][4];
#pragma unroll
    for (int i = 0; i < MI; i++)
#pragma unroll
        for (int j = 0; j < NJ; j++)
#pragma unroll
            for (int r = 0; r < 4; r++) acc[i][j][r] = 0.f;

    load_stage(0, 0);

    for (int kt = 0; kt < KT; kt++) {
        if (kt + 1 < KT) load_stage(kt + 1, (kt + 1) & 1);
        else CP_COMMIT();
        CP_WAIT1();
        __syncthreads();

        const uint32_t sa = sbase + (uint32_t)(kt & 1) * STAGE_BYTES;
#pragma unroll
        for (int ks = 0; ks < 4; ks++) {
            const uint32_t ksh = (uint32_t)(ks * 16) * 2;
            uint32_t a[MI][4];
#pragma unroll
            for (int i = 0; i < MI; i++)
                LDMX4(a[i][0], a[i][1], a[i][2], a[i][3],
                      sa + (aoffh + (uint32_t)(i * 16) * LDH) * 2 + ksh);
            uint32_t b[NJ][2];
#pragma unroll
            for (int jp = 0; jp < NJ / 2; jp++)
                LDMX4(b[jp * 2][0], b[jp * 2 + 1][0], b[jp * 2][1], b[jp * 2 + 1][1],
                      sa + (boffh + (uint32_t)(jp * 16) * LDH) * 2 + ksh);
#pragma unroll
            for (int i = 0; i < MI; i++)
#pragma unroll
                for (int j = 0; j < NJ; j++)
                    MMA_F16(acc[i][j], a[i], b[j]);
        }
        __syncthreads();
    }

    // Epilogue
#pragma unroll
    for (int i = 0; i < MI; i++) {
        int row0 = m0 + wm * 32 + i * 16 + g;
#pragma unroll
        for (int j = 0; j < NJ; j++) {
            int col = n0 + wn * 32 + j * 8 + 2 * t4;
            float bx = bias[col], by = bias[col + 1];
            float2 v0 = { acc[i][j][0] + bx, acc[i][j][1] + by };
            float2 v1 = { acc[i][j][2] + bx, acc[i][j][3] + by };
            *(float2*)(C + (long)row0 * DM + col)       = v0;
            *(float2*)(C + (long)(row0 + 8) * DM + col) = v1;
        }
    }
}

static constexpr int SMEM_B0 = NSTAGE * (64 + 128) * LDH * 2;  // 55296
static constexpr int SMEM_B1 = NSTAGE * (128 + 64) * LDH * 2;  // 55296

// ---------------------------------------------------------------------------
// Launch
// ---------------------------------------------------------------------------
extern "C" void kernel_launch(void* const* d_in, const int* in_sizes, int n_in,
                              void* d_out, int out_size) {
    const float* x    = (const float*)d_in[0];
    const float* Wg   = (const float*)d_in[1];
    const float* A    = (const float*)d_in[2];
    const float* B    = (const float*)d_in[3];
    const float* Wb   = (const float*)d_in[4];
    const float* bias = (const float*)d_in[5];
    float* out = (float*)d_out;

    static bool attr_done = false;
    if (!attr_done) {
        cudaFuncSetAttribute(gemm0_gate, cudaFuncAttributeMaxDynamicSharedMemorySize, SMEM_B0);
        cudaFuncSetAttribute(gemm1, cudaFuncAttributeMaxDynamicSharedMemorySize, SMEM_B1);
        attr_done = true;
    }

    __half *xh, *wh, *ah;
    cudaGetSymbolAddress((void**)&xh, g_xh);
    cudaGetSymbolAddress((void**)&wh, g_wh);
    cudaGetSymbolAddress((void**)&ah, g_ah);

    // 1) fp16 operand staging + fp32 gate logits/top-2 (one launch, overlapped)
    prep_logit_kernel<<<(int)(NPREP / 256), 256>>>(x, Wb, B, A, Wg);

    // 2) h-GEMM with fused gate epilogue -> writes c-tail of g_xh directly
    gemm0_gate<<<NTOK / 64, 256, SMEM_B0>>>(xh, ah);

    // 3) fused output GEMM: out = [x|c] @ [W|Bt]^T + bias  (8192 x 1024 x 1152)
    gemm1<<<dim3(NTOK / 128, DM / 64), 256, SMEM_B1>>>(xh, wh, out, bias);
}